// round 2
// baseline (speedup 1.0000x reference)
#include <cuda_runtime.h>

#define VOCAB 9
#define D     4
#define S     16384

#define NBLK  16
#define NTHR  256   // 8 warps; 16*256 = 4096 threads, 4 output rows each

// ---------------------------------------------------------------------------
// Single fused kernel.
//  Phase A (per block, redundant): detect int32/int64 layout of x, histogram
//           all 16384 tokens via warp ballots.
//  Phase B: 9-row math pipeline -> 9x9 probability table in shared.
//  Phase C: scatter — each thread writes 4 consecutive output rows
//           (4 rows x 9 floats = 144 B = 9 aligned float4 stores).
// ---------------------------------------------------------------------------
__global__ void __launch_bounds__(NTHR) bert_fused_kernel(
    const int* __restrict__ x32,
    const float* __restrict__ emb,
    const float* __restrict__ proj_w,
    const float* __restrict__ proj_b,
    const float* __restrict__ forw_w,
    const float* __restrict__ forw_b,
    const float* __restrict__ prj_w,
    const float* __restrict__ prj_b,
    float4* __restrict__ out4)
{
    __shared__ int   s_is64;
    __shared__ int   warp_cnt[8][VOCAB];
    __shared__ int   cnt[VOCAB];
    __shared__ float h0[VOCAB][D];
    __shared__ float sp[VOCAB * VOCAB];

    const int tid  = threadIdx.x;
    const int wid  = tid >> 5;
    const int lane = tid & 31;

    // ---- layout detection (warp 0): int64 little-endian => odd words zero,
    //      even words in [0,VOCAB). 64 words is in-bounds either way. ----
    if (wid == 0) {
        int e = __ldg(x32 + 2 * lane);
        int o = __ldg(x32 + 2 * lane + 1);
        int ok = (o == 0) && (e >= 0) && (e < VOCAB);
        unsigned all = __all_sync(0xffffffffu, ok);
        if (lane == 0) s_is64 = all ? 1 : 0;
    }
    __syncthreads();
    const int is64 = s_is64;

    // ---- histogram: 512 chunks of 32 tokens over 8 warps, ballot+popc.
    //      lane v (v < VOCAB) accumulates the count for value v. ----
    int myc = 0;
    for (int c = wid; c < S / 32; c += 8) {
        int tok = c * 32 + lane;
        int val = is64 ? __ldg(x32 + 2 * tok) : __ldg(x32 + tok);
        #pragma unroll
        for (int v = 0; v < VOCAB; v++) {
            unsigned m = __ballot_sync(0xffffffffu, val == v);
            if (lane == v) myc += __popc(m);
        }
    }
    if (lane < VOCAB) warp_cnt[wid][lane] = myc;
    __syncthreads();

    if (tid < VOCAB) {
        int s = 0;
        #pragma unroll
        for (int w = 0; w < 8; w++) s += warp_cnt[w][tid];
        cnt[tid] = s;
    }

    // ---- h0[v][d] = sum_k emb[v][k] * proj_w[d][k] + proj_b[d] ----
    if (tid >= 64 && tid < 64 + VOCAB * D) {
        int q = tid - 64;
        int v = q / D, d = q % D;
        float acc = __ldg(proj_b + d);
        #pragma unroll
        for (int k = 0; k < D; k++)
            acc += __ldg(emb + v * D + k) * __ldg(proj_w + d * D + k);
        h0[v][d] = acc;
    }
    __syncthreads();

    // ---- per-distinct-row pipeline (9 rows, one thread each) ----
    if (tid < VOCAB) {
        const int v = tid;
        float hv0 = h0[v][0], hv1 = h0[v][1], hv2 = h0[v][2], hv3 = h0[v][3];

        // scores against all 9 distinct rows
        float sc[VOCAB];
        float m = -3.4e38f;
        #pragma unroll
        for (int u = 0; u < VOCAB; u++) {
            float s = hv0 * h0[u][0] + hv1 * h0[u][1]
                    + hv2 * h0[u][2] + hv3 * h0[u][3];
            sc[u] = s;
            m = fmaxf(m, s);
        }

        // grouped softmax-weighted sum: attn @ h  (exact regrouping by token)
        float wsum = 0.f, a0 = 0.f, a1 = 0.f, a2 = 0.f, a3 = 0.f;
        #pragma unroll
        for (int u = 0; u < VOCAB; u++) {
            float e = expf(sc[u] - m) * (float)cnt[u];
            wsum += e;
            a0 += e * h0[u][0];
            a1 += e * h0[u][1];
            a2 += e * h0[u][2];
            a3 += e * h0[u][3];
        }
        float inv = 1.0f / wsum;
        float r[D];
        r[0] = fmaxf(0.f, a0 * inv);
        r[1] = fmaxf(0.f, a1 * inv);
        r[2] = fmaxf(0.f, a2 * inv);
        r[3] = fmaxf(0.f, a3 * inv);

        // h2 = r @ forw_w.T + forw_b
        float h2[D];
        #pragma unroll
        for (int d = 0; d < D; d++) {
            float acc = __ldg(forw_b + d);
            #pragma unroll
            for (int k = 0; k < D; k++)
                acc += __ldg(forw_w + d * D + k) * r[k];
            h2[d] = acc;
        }

        // logits = h2 @ prj_w.T + prj_b ; softmax over VOCAB
        float lg[VOCAB];
        float m2 = -3.4e38f;
        #pragma unroll
        for (int c = 0; c < VOCAB; c++) {
            float acc = __ldg(prj_b + c);
            #pragma unroll
            for (int k = 0; k < D; k++)
                acc += __ldg(prj_w + c * D + k) * h2[k];
            lg[c] = acc;
            m2 = fmaxf(m2, acc);
        }
        float zsum = 0.f;
        #pragma unroll
        for (int c = 0; c < VOCAB; c++) {
            lg[c] = expf(lg[c] - m2);
            zsum += lg[c];
        }
        float zinv = 1.0f / zsum;
        #pragma unroll
        for (int c = 0; c < VOCAB; c++)
            sp[v * VOCAB + c] = lg[c] * zinv;
    }
    __syncthreads();

    // ---- scatter: thread t owns output rows 4t .. 4t+3 ----
    const int t = blockIdx.x * NTHR + tid;   // 0..4095

    int vals[4];
    if (is64) {
        int4 a = __ldg((const int4*)x32 + 2 * t);
        int4 b = __ldg((const int4*)x32 + 2 * t + 1);
        vals[0] = a.x; vals[1] = a.z; vals[2] = b.x; vals[3] = b.z;
    } else {
        int4 a = __ldg((const int4*)x32 + t);
        vals[0] = a.x; vals[1] = a.y; vals[2] = a.z; vals[3] = a.w;
    }

    float4* o = out4 + (size_t)t * 9;
    #pragma unroll
    for (int k = 0; k < 9; k++) {
        float4 f;
        f.x = sp[vals[(4 * k + 0) / 9] * VOCAB + (4 * k + 0) % 9];
        f.y = sp[vals[(4 * k + 1) / 9] * VOCAB + (4 * k + 1) % 9];
        f.z = sp[vals[(4 * k + 2) / 9] * VOCAB + (4 * k + 2) % 9];
        f.w = sp[vals[(4 * k + 3) / 9] * VOCAB + (4 * k + 3) % 9];
        o[k] = f;
    }
}

extern "C" void kernel_launch(void* const* d_in, const int* in_sizes, int n_in,
                              void* d_out, int out_size)
{
    const int*   x      = (const int*)d_in[0];
    const float* emb    = (const float*)d_in[1];
    const float* proj_w = (const float*)d_in[2];
    const float* proj_b = (const float*)d_in[3];
    const float* forw_w = (const float*)d_in[4];
    const float* forw_b = (const float*)d_in[5];
    const float* prj_w  = (const float*)d_in[6];
    const float* prj_b  = (const float*)d_in[7];
    float* out = (float*)d_out;

    bert_fused_kernel<<<NBLK, NTHR>>>(x, emb, proj_w, proj_b,
                                      forw_w, forw_b, prj_w, prj_b,
                                      (float4*)out);
    (void)in_sizes; (void)n_in; (void)out_size;
}

// round 5
// speedup vs baseline: 2.1470x; 2.1470x over previous
#include <cuda_runtime.h>

#define VOCAB 9
#define D     4
#define S     16384

#define NBLK  16
#define NTHR  256   // 8 warps; 16*256 = 4096 threads, 4 output rows each

// ---------------------------------------------------------------------------
// Single fused kernel.
//  Phase A: speculative int32-interp batch load (16 int4/thread, MLP~16);
//           layout detection is a block consensus on that SAME data
//           (int64 LE <=> all odd words 0, even words in [0,9)), so the
//           int32 case pays exactly ONE exposed memory latency.
//           Histogram via ONE packed uint64 per thread (9 counters x 7 bits,
//           per-thread max 64 < 127). The j==blockIdx chunk doubles as this
//           thread's scatter payload (no reload after the barrier).
//  Phase B: 9-row math pipeline -> 9x9 probability table in shared.
//  Phase C: scatter — each thread writes 4 consecutive output rows
//           (4 rows x 9 floats = 144 B = 9 aligned float4 stores).
// ---------------------------------------------------------------------------
__global__ void __launch_bounds__(NTHR) bert_fused_kernel(
    const int* __restrict__ x32,
    const float* __restrict__ emb,
    const float* __restrict__ proj_w,
    const float* __restrict__ proj_b,
    const float* __restrict__ forw_w,
    const float* __restrict__ forw_b,
    const float* __restrict__ prj_w,
    const float* __restrict__ prj_b,
    float4* __restrict__ out4)
{
    __shared__ int   s_ok[8];
    __shared__ int   warp_cnt[8][VOCAB];
    __shared__ int   cnt[VOCAB];
    __shared__ float h0[VOCAB][D];
    __shared__ float sp[VOCAB * VOCAB];

    const int tid  = threadIdx.x;
    const int wid  = tid >> 5;
    const int lane = tid & 31;
    const int bid  = blockIdx.x;
    const int4* p4 = (const int4*)x32;

    // ---- Phase A1: speculative int32-interpretation loads (block-strided,
    //      coalesced; in-bounds under both layouts). ----
    int4 v[16];
    #pragma unroll
    for (int j = 0; j < 16; j++)
        v[j] = __ldg(p4 + tid + 256 * j);

    // ---- Phase A2: consensus layout detection on the loaded data ----
    bool ok = true;
    #pragma unroll
    for (int j = 0; j < 16; j++)
        ok = ok && (v[j].y == 0) && (v[j].w == 0)
                && ((unsigned)v[j].x < VOCAB) && ((unsigned)v[j].z < VOCAB);
    unsigned wall = __all_sync(0xffffffffu, ok);
    if (lane == 0) s_ok[wid] = (int)(wall != 0);
    __syncthreads();
    int is64 = 1;
    #pragma unroll
    for (int w = 0; w < 8; w++) is64 &= s_ok[w];

    // ---- Phase A3: count into packed accumulator; capture scatter payload.
    //      Chunk c covers output rows' tokens 4c..4c+3; thread handles chunks
    //      {tid + 256*j}; the j==bid chunk belongs to t = bid*256 + tid. ----
    unsigned long long acc = 0ULL;
    int vals[4] = {0, 0, 0, 0};

    if (is64) {
        // Real layout is int64: reload with correct addressing (2 int4/chunk,
        // tokens at .x and .z). 32 concurrent loads, one more latency.
        int4 u[32];
        #pragma unroll
        for (int j = 0; j < 16; j++) {
            int c = tid + 256 * j;
            u[2 * j]     = __ldg(p4 + 2 * c);
            u[2 * j + 1] = __ldg(p4 + 2 * c + 1);
        }
        #pragma unroll
        for (int j = 0; j < 16; j++) {
            int t0 = u[2 * j].x,     t1 = u[2 * j].z;
            int t2 = u[2 * j + 1].x, t3 = u[2 * j + 1].z;
            acc += 1ULL << (7 * t0);
            acc += 1ULL << (7 * t1);
            acc += 1ULL << (7 * t2);
            acc += 1ULL << (7 * t3);
            if (j == bid) { vals[0] = t0; vals[1] = t1; vals[2] = t2; vals[3] = t3; }
        }
    } else {
        #pragma unroll
        for (int j = 0; j < 16; j++) {
            acc += 1ULL << (7 * v[j].x);
            acc += 1ULL << (7 * v[j].y);
            acc += 1ULL << (7 * v[j].z);
            acc += 1ULL << (7 * v[j].w);
            if (j == bid) { vals[0] = v[j].x; vals[1] = v[j].y;
                            vals[2] = v[j].z; vals[3] = v[j].w; }
        }
    }

    // ---- reduce: unpack 9 counters, warp REDUX, then 8-warp sum ----
    #pragma unroll
    for (int q = 0; q < VOCAB; q++) {
        unsigned c = (unsigned)((acc >> (7 * q)) & 127ULL);
        unsigned ws = __reduce_add_sync(0xffffffffu, c);
        if (lane == 0) warp_cnt[wid][q] = (int)ws;
    }
    __syncthreads();

    if (tid < VOCAB) {
        int s = 0;
        #pragma unroll
        for (int w = 0; w < 8; w++) s += warp_cnt[w][tid];
        cnt[tid] = s;
    }

    // ---- h0[q][d] = sum_k emb[q][k] * proj_w[d][k] + proj_b[d] ----
    if (tid >= 64 && tid < 64 + VOCAB * D) {
        int q = tid - 64;
        int vv = q / D, d = q % D;
        float a = __ldg(proj_b + d);
        #pragma unroll
        for (int k = 0; k < D; k++)
            a += __ldg(emb + vv * D + k) * __ldg(proj_w + d * D + k);
        h0[vv][d] = a;
    }
    __syncthreads();

    // ---- per-distinct-row pipeline (9 rows, one thread each) ----
    if (tid < VOCAB) {
        const int vv = tid;
        float hv0 = h0[vv][0], hv1 = h0[vv][1], hv2 = h0[vv][2], hv3 = h0[vv][3];

        float sc[VOCAB];
        float m = -3.4e38f;
        #pragma unroll
        for (int u = 0; u < VOCAB; u++) {
            float s = hv0 * h0[u][0] + hv1 * h0[u][1]
                    + hv2 * h0[u][2] + hv3 * h0[u][3];
            sc[u] = s;
            m = fmaxf(m, s);
        }

        // grouped softmax-weighted sum: attn @ h (exact regrouping by token)
        float wsum = 0.f, a0 = 0.f, a1 = 0.f, a2 = 0.f, a3 = 0.f;
        #pragma unroll
        for (int u = 0; u < VOCAB; u++) {
            float e = expf(sc[u] - m) * (float)cnt[u];
            wsum += e;
            a0 += e * h0[u][0];
            a1 += e * h0[u][1];
            a2 += e * h0[u][2];
            a3 += e * h0[u][3];
        }
        float inv = 1.0f / wsum;
        float r[D];
        r[0] = fmaxf(0.f, a0 * inv);
        r[1] = fmaxf(0.f, a1 * inv);
        r[2] = fmaxf(0.f, a2 * inv);
        r[3] = fmaxf(0.f, a3 * inv);

        // h2 = r @ forw_w.T + forw_b
        float h2[D];
        #pragma unroll
        for (int d = 0; d < D; d++) {
            float a = __ldg(forw_b + d);
            #pragma unroll
            for (int k = 0; k < D; k++)
                a += __ldg(forw_w + d * D + k) * r[k];
            h2[d] = a;
        }

        // logits = h2 @ prj_w.T + prj_b ; softmax over VOCAB
        float lg[VOCAB];
        float m2 = -3.4e38f;
        #pragma unroll
        for (int c = 0; c < VOCAB; c++) {
            float a = __ldg(prj_b + c);
            #pragma unroll
            for (int k = 0; k < D; k++)
                a += __ldg(prj_w + c * D + k) * h2[k];
            lg[c] = a;
            m2 = fmaxf(m2, a);
        }
        float zsum = 0.f;
        #pragma unroll
        for (int c = 0; c < VOCAB; c++) {
            lg[c] = expf(lg[c] - m2);
            zsum += lg[c];
        }
        float zinv = 1.0f / zsum;
        #pragma unroll
        for (int c = 0; c < VOCAB; c++)
            sp[vv * VOCAB + c] = lg[c] * zinv;
    }
    __syncthreads();

    // ---- scatter: thread t owns output rows 4t .. 4t+3 (tokens already in
    //      vals[] from Phase A — no reload). ----
    const int t = bid * NTHR + tid;    // 0..4095

    float4* o = out4 + (size_t)t * 9;
    #pragma unroll
    for (int k = 0; k < 9; k++) {
        float4 f;
        f.x = sp[vals[(4 * k + 0) / 9] * VOCAB + (4 * k + 0) % 9];
        f.y = sp[vals[(4 * k + 1) / 9] * VOCAB + (4 * k + 1) % 9];
        f.z = sp[vals[(4 * k + 2) / 9] * VOCAB + (4 * k + 2) % 9];
        f.w = sp[vals[(4 * k + 3) / 9] * VOCAB + (4 * k + 3) % 9];
        o[k] = f;
    }
}

extern "C" void kernel_launch(void* const* d_in, const int* in_sizes, int n_in,
                              void* d_out, int out_size)
{
    const int*   x      = (const int*)d_in[0];
    const float* emb    = (const float*)d_in[1];
    const float* proj_w = (const float*)d_in[2];
    const float* proj_b = (const float*)d_in[3];
    const float* forw_w = (const float*)d_in[4];
    const float* forw_b = (const float*)d_in[5];
    const float* prj_w  = (const float*)d_in[6];
    const float* prj_b  = (const float*)d_in[7];
    float* out = (float*)d_out;

    bert_fused_kernel<<<NBLK, NTHR>>>(x, emb, proj_w, proj_b,
                                      forw_w, forw_b, prj_w, prj_b,
                                      (float4*)out);
    (void)in_sizes; (void)n_in; (void)out_size;
}